// round 4
// baseline (speedup 1.0000x reference)
#include <cuda_runtime.h>

// Problem dims (fixed)
#define T_  512
#define B_  256
#define F_  512
#define H_  128
#define G4_ 512   // 4*H
#define A_  8
#define MH_ 64

// Scratch (allocation-free rule: __device__ globals)
__device__ float g_xgates[(size_t)T_ * B_ * G4_];  // 256 MB: pre-computed x @ W_ih^T + biases
__device__ float g_hseq[(size_t)T_ * B_ * H_];     // 64 MB: per-step hidden states

// ---------------------------------------------------------------------------
// Fast activations (fp32, ~1e-6 rel err)
// ---------------------------------------------------------------------------
__device__ __forceinline__ float sigm_f(float x) {
    return 1.0f / (1.0f + __expf(-x));
}
__device__ __forceinline__ float tanh_f(float x) {
    // tanh(x) = 1 - 2/(1+e^{2x}); saturates correctly for |x| large (exp->0 or inf)
    float e = __expf(2.0f * x);
    return 1.0f - 2.0f / (e + 1.0f);
}

// ---------------------------------------------------------------------------
// Kernel 1: xgates = X[131072,512] @ W_ih^T[512,512] + (b_ih + b_hh)
// Classic 128x128x16 tiled SGEMM, 256 threads, 8x8 per-thread microtile.
// ---------------------------------------------------------------------------
__global__ __launch_bounds__(256, 2)
void gemm_xw_kernel(const float* __restrict__ X,
                    const float* __restrict__ Wih,
                    const float* __restrict__ bih,
                    const float* __restrict__ bhh)
{
    __shared__ float As[16][128];   // As[k][m]
    __shared__ float Bs[16][128];   // Bs[k][g]

    const int tid = threadIdx.x;
    const int bm  = blockIdx.x >> 2;       // 0..1023
    const int bn  = blockIdx.x & 3;        // 0..3
    const int m0  = bm * 128;
    const int g0  = bn * 128;

    const int tm = tid >> 4;   // 0..15
    const int tn = tid & 15;   // 0..15

    const int lr = tid >> 2;   // 0..63  loader row
    const int lc = tid & 3;    // 0..3   loader float4 col

    float acc[8][8];
#pragma unroll
    for (int i = 0; i < 8; i++)
#pragma unroll
        for (int j = 0; j < 8; j++) acc[i][j] = 0.0f;

    float bias[8];
#pragma unroll
    for (int j = 0; j < 8; j++) {
        int g = g0 + tn * 8 + j;
        bias[j] = bih[g] + bhh[g];
    }

    for (int kt = 0; kt < F_; kt += 16) {
#pragma unroll
        for (int it = 0; it < 2; it++) {
            int row = lr + it * 64;
            float4 v = *reinterpret_cast<const float4*>(X + (size_t)(m0 + row) * F_ + kt + lc * 4);
            As[lc * 4 + 0][row] = v.x;
            As[lc * 4 + 1][row] = v.y;
            As[lc * 4 + 2][row] = v.z;
            As[lc * 4 + 3][row] = v.w;
            float4 w = *reinterpret_cast<const float4*>(Wih + (size_t)(g0 + row) * F_ + kt + lc * 4);
            Bs[lc * 4 + 0][row] = w.x;
            Bs[lc * 4 + 1][row] = w.y;
            Bs[lc * 4 + 2][row] = w.z;
            Bs[lc * 4 + 3][row] = w.w;
        }
        __syncthreads();

#pragma unroll
        for (int k = 0; k < 16; k++) {
            float a[8], b[8];
            float4 a0 = *reinterpret_cast<const float4*>(&As[k][tm * 8]);
            float4 a1 = *reinterpret_cast<const float4*>(&As[k][tm * 8 + 4]);
            float4 b0 = *reinterpret_cast<const float4*>(&Bs[k][tn * 8]);
            float4 b1 = *reinterpret_cast<const float4*>(&Bs[k][tn * 8 + 4]);
            a[0]=a0.x; a[1]=a0.y; a[2]=a0.z; a[3]=a0.w; a[4]=a1.x; a[5]=a1.y; a[6]=a1.z; a[7]=a1.w;
            b[0]=b0.x; b[1]=b0.y; b[2]=b0.z; b[3]=b0.w; b[4]=b1.x; b[5]=b1.y; b[6]=b1.z; b[7]=b1.w;
#pragma unroll
            for (int i = 0; i < 8; i++)
#pragma unroll
                for (int j = 0; j < 8; j++)
                    acc[i][j] = fmaf(a[i], b[j], acc[i][j]);
        }
        __syncthreads();
    }

#pragma unroll
    for (int i = 0; i < 8; i++) {
        int m = m0 + tm * 8 + i;
        float4 o0 = make_float4(acc[i][0] + bias[0], acc[i][1] + bias[1],
                                acc[i][2] + bias[2], acc[i][3] + bias[3]);
        float4 o1 = make_float4(acc[i][4] + bias[4], acc[i][5] + bias[5],
                                acc[i][6] + bias[6], acc[i][7] + bias[7]);
        float* dst = g_xgates + (size_t)m * G4_ + g0 + tn * 8;
        *reinterpret_cast<float4*>(dst)     = o0;
        *reinterpret_cast<float4*>(dst + 4) = o1;
    }
}

// ---------------------------------------------------------------------------
// Kernel 2: persistent masked-LSTM recurrence.
// Grid = 128 blocks x 512 threads; block owns batch rows {2*bx, 2*bx+1} and
// loops over all T=512 steps (block-local sync only).
// W_hh split: cols 0..63 in registers (thread g owns row g), cols 64..127 in
// smem transposed as float4 (conflict-free LDS.128).
//
// Dynamic smem layout (floats):
//   [0      , 32768) Wsm  : float4[16*512], Wsm4[k4*512+g] = W_hh[g][64+4k4..+3]
//   [32768  , 33792) done_s[1024]  (t-major, 2 rows)
//   [33792  , 34048) h_s[2][128]
//   [34048  , 35072) gs [2][512]
// total = 140288 bytes
// ---------------------------------------------------------------------------
__global__ __launch_bounds__(512, 1)
void lstm_kernel(const float* __restrict__ done,
                 const float* __restrict__ h0,
                 const float* __restrict__ c0,
                 const float* __restrict__ Whh,
                 float* __restrict__ hT,
                 float* __restrict__ cT)
{
    extern __shared__ float sm[];
    float4* Wsm4   = reinterpret_cast<float4*>(sm);  // [8192] float4
    float*  done_s = sm + 32768;                     // [1024]
    float*  h_s    = sm + 33792;                     // [2][128]
    float*  gs     = sm + 34048;                     // [2][512]

    const int tid = threadIdx.x;
    const int g   = tid;               // gate row this thread computes (0..511)
    const int b0  = blockIdx.x * 2;

    // Register half of W_hh: W_hh[g][0:64]
    float Wreg[64];
    {
        const float4* wrow = reinterpret_cast<const float4*>(Whh + (size_t)g * H_);
#pragma unroll
        for (int k4 = 0; k4 < 16; k4++) {
            float4 v = wrow[k4];
            Wreg[k4 * 4 + 0] = v.x;
            Wreg[k4 * 4 + 1] = v.y;
            Wreg[k4 * 4 + 2] = v.z;
            Wreg[k4 * 4 + 3] = v.w;
        }
    }
    // Smem half: each thread fills its own gate row's cols 64..127
    {
        const float4* wrow2 = reinterpret_cast<const float4*>(Whh + (size_t)g * H_ + 64);
#pragma unroll
        for (int k4 = 0; k4 < 16; k4++)
            Wsm4[k4 * 512 + g] = wrow2[k4];
    }
    // done mask preload for this block's 2 batch rows
    for (int idx = tid; idx < 2 * T_; idx += 512) {
        int t = idx >> 1, bi2 = idx & 1;
        done_s[idx] = done[(size_t)t * B_ + b0 + bi2];
    }

    // Per-(b,j) state in registers of threads 0..255
    const int bi = tid >> 7;    // 0/1  (valid for tid<256)
    const int j  = tid & 127;
    float hreg = 0.0f, creg = 0.0f;
    if (tid < 256) {
        hreg = h0[(size_t)(b0 + bi) * H_ + j];
        creg = c0[(size_t)(b0 + bi) * H_ + j];
    }
    __syncthreads();

    const float4* h0v = reinterpret_cast<const float4*>(h_s);
    const float4* h1v = reinterpret_cast<const float4*>(h_s + 128);

#pragma unroll 1
    for (int t = 0; t < T_; t++) {
        // Step 1: apply done mask to carry, publish masked h
        if (tid < 256) {
            float m = 1.0f - done_s[t * 2 + bi];
            creg *= m;
            hreg *= m;
            h_s[bi * 128 + j] = hreg;
        }
        __syncthreads();

        // Step 2: gates[b][g] = xgate + <W_hh[g,:], h[b,:]>
        {
            const float* xg = g_xgates + ((size_t)t * B_ + b0) * G4_;
            float xg0 = xg[g];          // issued early; consumed after the dots
            float xg1 = xg[G4_ + g];

            float acc0 = 0.0f, acc1 = 0.0f, acc0b = 0.0f, acc1b = 0.0f;
            // register half (k = 0..63), h broadcast via float4 LDS
#pragma unroll
            for (int k4 = 0; k4 < 16; k4++) {
                float4 ha = h0v[k4];
                float4 hb = h1v[k4];
                acc0  = fmaf(Wreg[4 * k4 + 0], ha.x, acc0);
                acc0b = fmaf(Wreg[4 * k4 + 1], ha.y, acc0b);
                acc0  = fmaf(Wreg[4 * k4 + 2], ha.z, acc0);
                acc0b = fmaf(Wreg[4 * k4 + 3], ha.w, acc0b);
                acc1  = fmaf(Wreg[4 * k4 + 0], hb.x, acc1);
                acc1b = fmaf(Wreg[4 * k4 + 1], hb.y, acc1b);
                acc1  = fmaf(Wreg[4 * k4 + 2], hb.z, acc1);
                acc1b = fmaf(Wreg[4 * k4 + 3], hb.w, acc1b);
            }
            // smem half (k = 64..127), weights re-used for both batch rows
#pragma unroll
            for (int k4 = 0; k4 < 16; k4++) {
                float4 w  = Wsm4[k4 * 512 + g];
                float4 ha = h0v[16 + k4];
                float4 hb = h1v[16 + k4];
                acc0  = fmaf(w.x, ha.x, acc0);
                acc0b = fmaf(w.y, ha.y, acc0b);
                acc0  = fmaf(w.z, ha.z, acc0);
                acc0b = fmaf(w.w, ha.w, acc0b);
                acc1  = fmaf(w.x, hb.x, acc1);
                acc1b = fmaf(w.y, hb.y, acc1b);
                acc1  = fmaf(w.z, hb.z, acc1);
                acc1b = fmaf(w.w, hb.w, acc1b);
            }
            gs[g]       = acc0 + acc0b + xg0;
            gs[512 + g] = acc1 + acc1b + xg1;
        }
        __syncthreads();

        // Step 3: gate nonlinearities + state update (threads 0..255)
        if (tid < 256) {
            float gi = gs[bi * 512 +         j];
            float gf = gs[bi * 512 + 128  + j];
            float gg = gs[bi * 512 + 256  + j];
            float go = gs[bi * 512 + 384  + j];
            float iv = sigm_f(gi);
            float fv = sigm_f(gf);
            float gv = tanh_f(gg);
            float ov = sigm_f(go);
            creg = fmaf(fv, creg, iv * gv);
            hreg = ov * tanh_f(creg);
            g_hseq[((size_t)t * B_ + b0 + bi) * H_ + j] = hreg;
        }
        // no barrier needed here: next step's barrier after Step 1 orders
        // gs reads (Step 3) before the next gs writes (Step 2).
    }

    if (tid < 256) {
        hT[(size_t)(b0 + bi) * H_ + j] = hreg;
        cT[(size_t)(b0 + bi) * H_ + j] = creg;
    }
}

// ---------------------------------------------------------------------------
// Kernel 3: heads. Block = 256 threads = 256 rows of hseq.
// Dynamic smem layout (floats):
//   h_s : [256][129] padded        = 33024
//   wp1 : [128*64]                 at 33024
//   wv1 : [128*64]                 at 41216
//   wp2 : [64*8]                   at 49408
//   wv2 : [64]                     at 49920
//   sbp1: [64]                     at 49984
//   sbv1: [64]                     at 50048
// total = 50112 floats = 200448 bytes
// ---------------------------------------------------------------------------
__global__ __launch_bounds__(256, 1)
void heads_kernel(const float* __restrict__ Wp1, const float* __restrict__ bp1,
                  const float* __restrict__ Wp2, const float* __restrict__ bp2,
                  const float* __restrict__ Wv1, const float* __restrict__ bv1,
                  const float* __restrict__ Wv2, const float* __restrict__ bv2,
                  float* __restrict__ out)
{
    extern __shared__ float sm[];
    float* h_s  = sm;            // [256][129]
    float* wp1  = sm + 33024;    // [8192]
    float* wv1  = sm + 41216;    // [8192]
    float* wp2  = sm + 49408;    // [512]
    float* wv2  = sm + 49920;    // [64]
    float* sbp1 = sm + 49984;    // [64]
    float* sbv1 = sm + 50048;    // [64]

    const int tid = threadIdx.x;
    const size_t row0 = (size_t)blockIdx.x * 256;

    // cooperative h-tile load (padded stride 129)
    for (int idx = tid; idx < 256 * 32; idx += 256) {
        int r  = idx >> 5;
        int c4 = idx & 31;
        float4 v = reinterpret_cast<const float4*>(g_hseq + (row0 + r) * H_)[c4];
        float* dst = h_s + r * 129 + c4 * 4;
        dst[0] = v.x; dst[1] = v.y; dst[2] = v.z; dst[3] = v.w;
    }
    for (int idx = tid; idx < H_ * MH_; idx += 256) {
        wp1[idx] = Wp1[idx];
        wv1[idx] = Wv1[idx];
    }
    for (int idx = tid; idx < MH_ * A_; idx += 256) wp2[idx] = Wp2[idx];
    if (tid < 64) {
        wv2[tid]  = Wv2[tid];
        sbp1[tid] = bp1[tid];
        sbv1[tid] = bv1[tid];
    }
    __syncthreads();

    float ap[64], av[64];
#pragma unroll
    for (int i = 0; i < 64; i++) { ap[i] = 0.0f; av[i] = 0.0f; }

    const float*  hrow = h_s + tid * 129;
    const float4* wp1v = reinterpret_cast<const float4*>(wp1);
    const float4* wv1v = reinterpret_cast<const float4*>(wv1);

#pragma unroll 1
    for (int k = 0; k < H_; k++) {
        float hk = hrow[k];
#pragma unroll
        for (int m4 = 0; m4 < 16; m4++) {
            float4 wp = wp1v[k * 16 + m4];
            float4 wv = wv1v[k * 16 + m4];
            ap[m4 * 4 + 0] = fmaf(hk, wp.x, ap[m4 * 4 + 0]);
            ap[m4 * 4 + 1] = fmaf(hk, wp.y, ap[m4 * 4 + 1]);
            ap[m4 * 4 + 2] = fmaf(hk, wp.z, ap[m4 * 4 + 2]);
            ap[m4 * 4 + 3] = fmaf(hk, wp.w, ap[m4 * 4 + 3]);
            av[m4 * 4 + 0] = fmaf(hk, wv.x, av[m4 * 4 + 0]);
            av[m4 * 4 + 1] = fmaf(hk, wv.y, av[m4 * 4 + 1]);
            av[m4 * 4 + 2] = fmaf(hk, wv.z, av[m4 * 4 + 2]);
            av[m4 * 4 + 3] = fmaf(hk, wv.w, av[m4 * 4 + 3]);
        }
    }

    float lg[8];
#pragma unroll
    for (int a = 0; a < 8; a++) lg[a] = bp2[a];
    float v = bv2[0];

#pragma unroll
    for (int mh = 0; mh < 64; mh++) {
        float tp = tanh_f(ap[mh] + sbp1[mh]);
        float tv = tanh_f(av[mh] + sbv1[mh]);
        v = fmaf(tv, wv2[mh], v);
#pragma unroll
        for (int a = 0; a < 8; a++)
            lg[a] = fmaf(tp, wp2[mh * 8 + a], lg[a]);
    }

    float* orow = out + (row0 + tid) * 9;
#pragma unroll
    for (int a = 0; a < 8; a++) orow[a] = lg[a];
    orow[8] = v;
}

// ---------------------------------------------------------------------------
// Launch
// ---------------------------------------------------------------------------
extern "C" void kernel_launch(void* const* d_in, const int* in_sizes, int n_in,
                              void* d_out, int out_size)
{
    (void)in_sizes; (void)n_in; (void)out_size;

    const float* x    = (const float*)d_in[0];
    const float* done = (const float*)d_in[1];
    const float* h0   = (const float*)d_in[2];
    const float* c0   = (const float*)d_in[3];
    const float* Wih  = (const float*)d_in[4];
    const float* Whh  = (const float*)d_in[5];
    const float* bih  = (const float*)d_in[6];
    const float* bhh  = (const float*)d_in[7];
    const float* Wp1  = (const float*)d_in[8];
    const float* bp1  = (const float*)d_in[9];
    const float* Wp2  = (const float*)d_in[10];
    const float* bp2  = (const float*)d_in[11];
    const float* Wv1  = (const float*)d_in[12];
    const float* bv1  = (const float*)d_in[13];
    const float* Wv2  = (const float*)d_in[14];
    const float* bv2  = (const float*)d_in[15];

    float* out = (float*)d_out;
    float* hT  = out + (size_t)T_ * B_ * (A_ + 1);   // after [T*B, 9]
    float* cT  = hT + (size_t)B_ * H_;

    const int lstm_smem  = 35072 * 4;   // 140288 B
    const int heads_smem = 50112 * 4;   // 200448 B
    cudaFuncSetAttribute(lstm_kernel,  cudaFuncAttributeMaxDynamicSharedMemorySize, lstm_smem);
    cudaFuncSetAttribute(heads_kernel, cudaFuncAttributeMaxDynamicSharedMemorySize, heads_smem);

    // 1) input projection: 1024 m-tiles x 4 n-tiles
    gemm_xw_kernel<<<4096, 256>>>(x, Wih, bih, bhh);
    // 2) recurrence: 128 persistent blocks (2 batch rows each)
    lstm_kernel<<<128, 512, lstm_smem>>>(done, h0, c0, Whh, hT, cT);
    // 3) heads: 512 blocks x 256 rows
    heads_kernel<<<512, 256, heads_smem>>>(Wp1, bp1, Wp2, bp2, Wv1, bv1, Wv2, bv2, out);
}

// round 5
// speedup vs baseline: 1.0042x; 1.0042x over previous
#include <cuda_runtime.h>

// Problem dims (fixed)
#define T_  512
#define B_  256
#define F_  512
#define H_  128
#define G4_ 512   // 4*H
#define A_  8
#define MH_ 64

// Scratch (allocation-free rule: __device__ globals)
__device__ float g_xgates[(size_t)T_ * B_ * G4_];  // 256 MB: pre-computed x @ W_ih^T + biases
__device__ float g_hseq[(size_t)T_ * B_ * H_];     // 64 MB: per-step hidden states

// ---------------------------------------------------------------------------
// Fast activations (fp32, ~1e-6 rel err)
// ---------------------------------------------------------------------------
__device__ __forceinline__ float sigm_f(float x) {
    return 1.0f / (1.0f + __expf(-x));
}
__device__ __forceinline__ float tanh_f(float x) {
    float e = __expf(2.0f * x);
    return 1.0f - 2.0f / (e + 1.0f);
}

// ---------------------------------------------------------------------------
// Kernel 1: xgates = X[131072,512] @ W_ih^T[512,512] + (b_ih + b_hh)
// Classic 128x128x16 tiled SGEMM, 256 threads, 8x8 per-thread microtile.
// (At the fp32 FFMA structural ceiling; unchanged this round.)
// ---------------------------------------------------------------------------
__global__ __launch_bounds__(256, 2)
void gemm_xw_kernel(const float* __restrict__ X,
                    const float* __restrict__ Wih,
                    const float* __restrict__ bih,
                    const float* __restrict__ bhh)
{
    __shared__ float As[16][128];   // As[k][m]
    __shared__ float Bs[16][128];   // Bs[k][g]

    const int tid = threadIdx.x;
    const int bm  = blockIdx.x >> 2;
    const int bn  = blockIdx.x & 3;
    const int m0  = bm * 128;
    const int g0  = bn * 128;

    const int tm = tid >> 4;
    const int tn = tid & 15;

    const int lr = tid >> 2;
    const int lc = tid & 3;

    float acc[8][8];
#pragma unroll
    for (int i = 0; i < 8; i++)
#pragma unroll
        for (int j = 0; j < 8; j++) acc[i][j] = 0.0f;

    float bias[8];
#pragma unroll
    for (int j = 0; j < 8; j++) {
        int g = g0 + tn * 8 + j;
        bias[j] = bih[g] + bhh[g];
    }

    for (int kt = 0; kt < F_; kt += 16) {
#pragma unroll
        for (int it = 0; it < 2; it++) {
            int row = lr + it * 64;
            float4 v = *reinterpret_cast<const float4*>(X + (size_t)(m0 + row) * F_ + kt + lc * 4);
            As[lc * 4 + 0][row] = v.x;
            As[lc * 4 + 1][row] = v.y;
            As[lc * 4 + 2][row] = v.z;
            As[lc * 4 + 3][row] = v.w;
            float4 w = *reinterpret_cast<const float4*>(Wih + (size_t)(g0 + row) * F_ + kt + lc * 4);
            Bs[lc * 4 + 0][row] = w.x;
            Bs[lc * 4 + 1][row] = w.y;
            Bs[lc * 4 + 2][row] = w.z;
            Bs[lc * 4 + 3][row] = w.w;
        }
        __syncthreads();

#pragma unroll
        for (int k = 0; k < 16; k++) {
            float a[8], b[8];
            float4 a0 = *reinterpret_cast<const float4*>(&As[k][tm * 8]);
            float4 a1 = *reinterpret_cast<const float4*>(&As[k][tm * 8 + 4]);
            float4 b0 = *reinterpret_cast<const float4*>(&Bs[k][tn * 8]);
            float4 b1 = *reinterpret_cast<const float4*>(&Bs[k][tn * 8 + 4]);
            a[0]=a0.x; a[1]=a0.y; a[2]=a0.z; a[3]=a0.w; a[4]=a1.x; a[5]=a1.y; a[6]=a1.z; a[7]=a1.w;
            b[0]=b0.x; b[1]=b0.y; b[2]=b0.z; b[3]=b0.w; b[4]=b1.x; b[5]=b1.y; b[6]=b1.z; b[7]=b1.w;
#pragma unroll
            for (int i = 0; i < 8; i++)
#pragma unroll
                for (int j = 0; j < 8; j++)
                    acc[i][j] = fmaf(a[i], b[j], acc[i][j]);
        }
        __syncthreads();
    }

#pragma unroll
    for (int i = 0; i < 8; i++) {
        int m = m0 + tm * 8 + i;
        float4 o0 = make_float4(acc[i][0] + bias[0], acc[i][1] + bias[1],
                                acc[i][2] + bias[2], acc[i][3] + bias[3]);
        float4 o1 = make_float4(acc[i][4] + bias[4], acc[i][5] + bias[5],
                                acc[i][6] + bias[6], acc[i][7] + bias[7]);
        float* dst = g_xgates + (size_t)m * G4_ + g0 + tn * 8;
        *reinterpret_cast<float4*>(dst)     = o0;
        *reinterpret_cast<float4*>(dst + 4) = o1;
    }
}

// ---------------------------------------------------------------------------
// Kernel 2: persistent masked-LSTM recurrence (rebalanced W split).
// Grid = 128 blocks x 512 threads; block owns batch rows {2*bx, 2*bx+1}.
// W_hh split: cols 0..31 in registers (32 regs/thread — no spill risk),
// cols 32..127 in smem transposed as float4 (conflict-free LDS.128).
//
// Dynamic smem layout (floats):
//   [0     , 49152) Wsm4 : float4[24*512], Wsm4[k4*512+g] = W_hh[g][32+4k4..+3]
//   [49152 , 50176) done_s[1024]  (t-major, 2 rows)
//   [50176 , 50432) h_s[2][128]
//   [50432 , 51456) gs [2][512]
// total = 51456 floats = 205824 bytes
// ---------------------------------------------------------------------------
__global__ __launch_bounds__(512, 1)
void lstm_kernel(const float* __restrict__ done,
                 const float* __restrict__ h0,
                 const float* __restrict__ c0,
                 const float* __restrict__ Whh,
                 float* __restrict__ hT,
                 float* __restrict__ cT)
{
    extern __shared__ float sm[];
    float4* Wsm4   = reinterpret_cast<float4*>(sm);  // [24*512] float4
    float*  done_s = sm + 49152;                     // [1024]
    float*  h_s    = sm + 50176;                     // [2][128]
    float*  gs     = sm + 50432;                     // [2][512]

    const int tid = threadIdx.x;
    const int g   = tid;               // gate row this thread computes (0..511)
    const int b0  = blockIdx.x * 2;

    // Register part of W_hh: W_hh[g][0:32]  (32 regs)
    float Wreg[32];
    {
        const float4* wrow = reinterpret_cast<const float4*>(Whh + (size_t)g * H_);
#pragma unroll
        for (int k4 = 0; k4 < 8; k4++) {
            float4 v = wrow[k4];
            Wreg[k4 * 4 + 0] = v.x;
            Wreg[k4 * 4 + 1] = v.y;
            Wreg[k4 * 4 + 2] = v.z;
            Wreg[k4 * 4 + 3] = v.w;
        }
        // Smem part: cols 32..127 of this thread's gate row
#pragma unroll
        for (int k4 = 0; k4 < 24; k4++)
            Wsm4[k4 * 512 + g] = wrow[8 + k4];
    }
    // done-mask preload for this block's 2 batch rows
    for (int idx = tid; idx < 2 * T_; idx += 512) {
        int t = idx >> 1, bi2 = idx & 1;
        done_s[idx] = done[(size_t)t * B_ + b0 + bi2];
    }

    // Per-(b,j) state in registers of threads 0..255
    const int bi = tid >> 7;    // 0/1  (valid for tid<256)
    const int j  = tid & 127;
    float creg = 0.0f;
    if (tid < 256) {
        float hreg = h0[(size_t)(b0 + bi) * H_ + j];
        creg = c0[(size_t)(b0 + bi) * H_ + j];
        // prologue: mask for t=0 and publish h
        float m = 1.0f - done_s[bi];
        creg *= m;
        h_s[bi * 128 + j] = hreg * m;
    }
    __syncthreads();

    const float4* h0v = reinterpret_cast<const float4*>(h_s);
    const float4* h1v = reinterpret_cast<const float4*>(h_s + 128);

    float hfin = 0.0f;   // final h (threads < 256)

#pragma unroll 1
    for (int t = 0; t < T_; t++) {
        // ---- Step A: gates[b][g] = xgate + <W_hh[g,:], h[b,:]> (all threads)
        {
            const float* xg = g_xgates + ((size_t)t * B_ + b0) * G4_;
            float xg0 = xg[g];          // issued early; consumed after the dots
            float xg1 = xg[G4_ + g];

            float acc0 = 0.0f, acc1 = 0.0f, acc0b = 0.0f, acc1b = 0.0f;
            // register half (cols 0..31), h broadcast via float4 LDS
#pragma unroll
            for (int k4 = 0; k4 < 8; k4++) {
                float4 ha = h0v[k4];
                float4 hb = h1v[k4];
                acc0  = fmaf(Wreg[4 * k4 + 0], ha.x, acc0);
                acc0b = fmaf(Wreg[4 * k4 + 1], ha.y, acc0b);
                acc0  = fmaf(Wreg[4 * k4 + 2], ha.z, acc0);
                acc0b = fmaf(Wreg[4 * k4 + 3], ha.w, acc0b);
                acc1  = fmaf(Wreg[4 * k4 + 0], hb.x, acc1);
                acc1b = fmaf(Wreg[4 * k4 + 1], hb.y, acc1b);
                acc1  = fmaf(Wreg[4 * k4 + 2], hb.z, acc1);
                acc1b = fmaf(Wreg[4 * k4 + 3], hb.w, acc1b);
            }
            // smem half (cols 32..127); bounded unroll caps live LDS ranges
#pragma unroll 4
            for (int k4 = 0; k4 < 24; k4++) {
                float4 w  = Wsm4[k4 * 512 + g];
                float4 ha = h0v[8 + k4];
                float4 hb = h1v[8 + k4];
                acc0  = fmaf(w.x, ha.x, acc0);
                acc0b = fmaf(w.y, ha.y, acc0b);
                acc0  = fmaf(w.z, ha.z, acc0);
                acc0b = fmaf(w.w, ha.w, acc0b);
                acc1  = fmaf(w.x, hb.x, acc1);
                acc1b = fmaf(w.y, hb.y, acc1b);
                acc1  = fmaf(w.z, hb.z, acc1);
                acc1b = fmaf(w.w, hb.w, acc1b);
            }
            gs[g]       = acc0 + acc0b + xg0;
            gs[512 + g] = acc1 + acc1b + xg1;
        }
        __syncthreads();

        // ---- Step B: nonlinearities + state update + mask-for-(t+1) + publish
        if (tid < 256) {
            float gi = gs[bi * 512 +        j];
            float gf = gs[bi * 512 + 128 + j];
            float gg = gs[bi * 512 + 256 + j];
            float go = gs[bi * 512 + 384 + j];
            float iv = sigm_f(gi);
            float fv = sigm_f(gf);
            float gv = tanh_f(gg);
            float ov = sigm_f(go);
            creg = fmaf(fv, creg, iv * gv);
            float hv = ov * tanh_f(creg);
            g_hseq[((size_t)t * B_ + b0 + bi) * H_ + j] = hv;
            if (t + 1 < T_) {
                float m = 1.0f - done_s[(t + 1) * 2 + bi];
                creg *= m;
                h_s[bi * 128 + j] = hv * m;
            } else {
                hfin = hv;
            }
        }
        __syncthreads();   // h published & gs drained before next step's writes
    }

    if (tid < 256) {
        hT[(size_t)(b0 + bi) * H_ + j] = hfin;
        cT[(size_t)(b0 + bi) * H_ + j] = creg;
    }
}

// ---------------------------------------------------------------------------
// Kernel 3: heads. Block = 256 threads = 256 rows of hseq. (unchanged)
// ---------------------------------------------------------------------------
__global__ __launch_bounds__(256, 1)
void heads_kernel(const float* __restrict__ Wp1, const float* __restrict__ bp1,
                  const float* __restrict__ Wp2, const float* __restrict__ bp2,
                  const float* __restrict__ Wv1, const float* __restrict__ bv1,
                  const float* __restrict__ Wv2, const float* __restrict__ bv2,
                  float* __restrict__ out)
{
    extern __shared__ float sm[];
    float* h_s  = sm;            // [256][129]
    float* wp1  = sm + 33024;    // [8192]
    float* wv1  = sm + 41216;    // [8192]
    float* wp2  = sm + 49408;    // [512]
    float* wv2  = sm + 49920;    // [64]
    float* sbp1 = sm + 49984;    // [64]
    float* sbv1 = sm + 50048;    // [64]

    const int tid = threadIdx.x;
    const size_t row0 = (size_t)blockIdx.x * 256;

    for (int idx = tid; idx < 256 * 32; idx += 256) {
        int r  = idx >> 5;
        int c4 = idx & 31;
        float4 v = reinterpret_cast<const float4*>(g_hseq + (row0 + r) * H_)[c4];
        float* dst = h_s + r * 129 + c4 * 4;
        dst[0] = v.x; dst[1] = v.y; dst[2] = v.z; dst[3] = v.w;
    }
    for (int idx = tid; idx < H_ * MH_; idx += 256) {
        wp1[idx] = Wp1[idx];
        wv1[idx] = Wv1[idx];
    }
    for (int idx = tid; idx < MH_ * A_; idx += 256) wp2[idx] = Wp2[idx];
    if (tid < 64) {
        wv2[tid]  = Wv2[tid];
        sbp1[tid] = bp1[tid];
        sbv1[tid] = bv1[tid];
    }
    __syncthreads();

    float ap[64], av[64];
#pragma unroll
    for (int i = 0; i < 64; i++) { ap[i] = 0.0f; av[i] = 0.0f; }

    const float*  hrow = h_s + tid * 129;
    const float4* wp1v = reinterpret_cast<const float4*>(wp1);
    const float4* wv1v = reinterpret_cast<const float4*>(wv1);

#pragma unroll 1
    for (int k = 0; k < H_; k++) {
        float hk = hrow[k];
#pragma unroll
        for (int m4 = 0; m4 < 16; m4++) {
            float4 wp = wp1v[k * 16 + m4];
            float4 wv = wv1v[k * 16 + m4];
            ap[m4 * 4 + 0] = fmaf(hk, wp.x, ap[m4 * 4 + 0]);
            ap[m4 * 4 + 1] = fmaf(hk, wp.y, ap[m4 * 4 + 1]);
            ap[m4 * 4 + 2] = fmaf(hk, wp.z, ap[m4 * 4 + 2]);
            ap[m4 * 4 + 3] = fmaf(hk, wp.w, ap[m4 * 4 + 3]);
            av[m4 * 4 + 0] = fmaf(hk, wv.x, av[m4 * 4 + 0]);
            av[m4 * 4 + 1] = fmaf(hk, wv.y, av[m4 * 4 + 1]);
            av[m4 * 4 + 2] = fmaf(hk, wv.z, av[m4 * 4 + 2]);
            av[m4 * 4 + 3] = fmaf(hk, wv.w, av[m4 * 4 + 3]);
        }
    }

    float lg[8];
#pragma unroll
    for (int a = 0; a < 8; a++) lg[a] = bp2[a];
    float v = bv2[0];

#pragma unroll
    for (int mh = 0; mh < 64; mh++) {
        float tp = tanh_f(ap[mh] + sbp1[mh]);
        float tv = tanh_f(av[mh] + sbv1[mh]);
        v = fmaf(tv, wv2[mh], v);
#pragma unroll
        for (int a = 0; a < 8; a++)
            lg[a] = fmaf(tp, wp2[mh * 8 + a], lg[a]);
    }

    float* orow = out + (row0 + tid) * 9;
#pragma unroll
    for (int a = 0; a < 8; a++) orow[a] = lg[a];
    orow[8] = v;
}

// ---------------------------------------------------------------------------
// Launch
// ---------------------------------------------------------------------------
extern "C" void kernel_launch(void* const* d_in, const int* in_sizes, int n_in,
                              void* d_out, int out_size)
{
    (void)in_sizes; (void)n_in; (void)out_size;

    const float* x    = (const float*)d_in[0];
    const float* done = (const float*)d_in[1];
    const float* h0   = (const float*)d_in[2];
    const float* c0   = (const float*)d_in[3];
    const float* Wih  = (const float*)d_in[4];
    const float* Whh  = (const float*)d_in[5];
    const float* bih  = (const float*)d_in[6];
    const float* bhh  = (const float*)d_in[7];
    const float* Wp1  = (const float*)d_in[8];
    const float* bp1  = (const float*)d_in[9];
    const float* Wp2  = (const float*)d_in[10];
    const float* bp2  = (const float*)d_in[11];
    const float* Wv1  = (const float*)d_in[12];
    const float* bv1  = (const float*)d_in[13];
    const float* Wv2  = (const float*)d_in[14];
    const float* bv2  = (const float*)d_in[15];

    float* out = (float*)d_out;
    float* hT  = out + (size_t)T_ * B_ * (A_ + 1);   // after [T*B, 9]
    float* cT  = hT + (size_t)B_ * H_;

    const int lstm_smem  = 51456 * 4;   // 205824 B
    const int heads_smem = 50112 * 4;   // 200448 B
    cudaFuncSetAttribute(lstm_kernel,  cudaFuncAttributeMaxDynamicSharedMemorySize, lstm_smem);
    cudaFuncSetAttribute(heads_kernel, cudaFuncAttributeMaxDynamicSharedMemorySize, heads_smem);

    // 1) input projection: 1024 m-tiles x 4 n-tiles
    gemm_xw_kernel<<<4096, 256>>>(x, Wih, bih, bhh);
    // 2) recurrence: 128 persistent blocks (2 batch rows each)
    lstm_kernel<<<128, 512, lstm_smem>>>(done, h0, c0, Whh, hT, cT);
    // 3) heads: 512 blocks x 256 rows
    heads_kernel<<<512, 256, heads_smem>>>(Wp1, bp1, Wp2, bp2, Wv1, bv1, Wv2, bv2, out);
}